// round 15
// baseline (speedup 1.0000x reference)
#include <cuda_runtime.h>
#include <cuda_fp16.h>
#include <cstdint>

#define BB 4
#define NN 4096
#define FF 128
#define ALPHA 0.1f
#define KC 64

// ---------------- device scratch ----------------
__device__ float g_w1[FF], g_w2[FF], g_c[2];
__device__ __align__(16) float2 g_e1[BB * NN];
__device__ __align__(16) float2 g_e2[BB * NN];
__device__ __align__(16) __half g_vph[BB * NN * FF];            // fp16 [b][j][f]
__device__ __align__(16) __half g_woh[FF * FF];
__device__ __align__(16) __half g_wol[FF * FF];

__device__ __forceinline__ float leaky(float x) { return fmaxf(x, ALPHA * x); }

// ---------------- mma.sync helpers ----------------
__device__ __forceinline__ void mma16816(float* d, const uint32_t* a, const uint32_t* b) {
    asm volatile("mma.sync.aligned.m16n8k16.row.col.f32.f16.f16.f32 "
        "{%0,%1,%2,%3},{%4,%5,%6,%7},{%8,%9},{%0,%1,%2,%3};"
        : "+f"(d[0]), "+f"(d[1]), "+f"(d[2]), "+f"(d[3])
        : "r"(a[0]), "r"(a[1]), "r"(a[2]), "r"(a[3]), "r"(b[0]), "r"(b[1]));
}
__device__ __forceinline__ void ldsm_x4(uint32_t* r, uint32_t addr) {
    asm volatile("ldmatrix.sync.aligned.m8n8.x4.shared.b16 {%0,%1,%2,%3},[%4];"
        : "=r"(r[0]), "=r"(r[1]), "=r"(r[2]), "=r"(r[3]) : "r"(addr));
}
__device__ __forceinline__ void ldsm_x4_t(uint32_t* r, uint32_t addr) {
    asm volatile("ldmatrix.sync.aligned.m8n8.x4.trans.shared.b16 {%0,%1,%2,%3},[%4];"
        : "=r"(r[0]), "=r"(r[1]), "=r"(r[2]), "=r"(r[3]) : "r"(addr));
}
__device__ __forceinline__ uint32_t smem_u32(const void* p) {
    uint32_t a;
    asm("{ .reg .u64 t; cvta.to.shared.u64 t, %1; cvt.u32.u64 %0, t; }" : "=r"(a) : "l"(p));
    return a;
}
__device__ __forceinline__ void cp16(uint32_t dst, const void* src) {
    asm volatile("cp.async.cg.shared.global [%0], [%1], 16;" :: "r"(dst), "l"(src) : "memory");
}
#define CP_COMMIT() asm volatile("cp.async.commit_group;" ::: "memory")
#define CP_WAIT0()  asm volatile("cp.async.wait_group 0;" ::: "memory")
#define CP_WAIT1()  asm volatile("cp.async.wait_group 1;" ::: "memory")
#define BARS(id)    asm volatile("bar.sync %0, 512;"   :: "r"(id) : "memory")
#define BARA(id)    asm volatile("bar.arrive %0, 512;" :: "r"(id) : "memory")
__device__ __forceinline__ uint32_t h2u(__half2 h) { return *(uint32_t*)&h; }

// ---------------- kernel 1: fold a into Q/K projections ----------------
__global__ void k_prep(const float* __restrict__ Wq_w, const float* __restrict__ Wq_b,
                       const float* __restrict__ Wk_w, const float* __restrict__ Wk_b,
                       const float* __restrict__ a) {
    int f = threadIdx.x;
    float s1 = 0.f, s2 = 0.f;
    for (int o = 0; o < FF; o++) {
        s1 += Wq_w[o * FF + f] * a[o];
        s2 += Wk_w[o * FF + f] * a[FF + o];
    }
    g_w1[f] = s1; g_w2[f] = s2;
    if (f == 0) {
        float c1 = 0.f, c2 = 0.f;
        for (int o = 0; o < FF; o++) { c1 += Wq_b[o] * a[o]; c2 += Wk_b[o] * a[FF + o]; }
        g_c[0] = c1; g_c[1] = c2;
    }
}

// ---------------- kernel 2: Wh -> (exp(wh), exp(0.1 wh)) pairs -------------
__global__ void k_wh(const float* __restrict__ q, const float* __restrict__ k) {
    int warp = threadIdx.x >> 5, lane = threadIdx.x & 31;
    int row = blockIdx.x * 8 + warp;
    const float* src; const float* w; float c; float2* dst; int r;
    if (row < BB * NN) { src = q; w = g_w1; c = g_c[0]; dst = g_e1; r = row; }
    else               { src = k; w = g_w2; c = g_c[1]; dst = g_e2; r = row - BB * NN; }
    float4 x  = ((const float4*)(src + (size_t)r * FF))[lane];
    float4 ww = ((const float4*)w)[lane];
    float s = x.x * ww.x + x.y * ww.y + x.z * ww.z + x.w * ww.w;
    #pragma unroll
    for (int o = 16; o > 0; o >>= 1) s += __shfl_xor_sync(0xffffffffu, s, o);
    if (lane == 0) {
        float wh = s + c;
        dst[r] = make_float2(__expf(wh), __expf(ALPHA * wh));
    }
}

// ---------------- kernel 3: V projection, tensor core ----------------------
#define GSTR 272
#define GX_HI 0
#define GX_LO 34816
#define GW_HI 69632
#define GW_LO 104448
#define G_TOTAL 139264

__global__ void __launch_bounds__(256, 1)
k_gemm_tc(const float* __restrict__ in, const float* __restrict__ W,
          const float* __restrict__ bias, __half* __restrict__ outh) {
    extern __shared__ char sm[];
    int t = threadIdx.x, lane = t & 31, wid = t >> 5;
    int i0 = blockIdx.x * 128;
    uint32_t sb = smem_u32(sm);

    #pragma unroll
    for (int kk = 0; kk < 16; kk++) {
        int e = t + kk * 256;
        int row = e >> 5, f4 = e & 31;
        int off = row * GSTR + f4 * 8;
        float4 xv = *(const float4*)(in + (size_t)(i0 + row) * FF + f4 * 4);
        __half2 xh01 = __floats2half2_rn(xv.x, xv.y);
        __half2 xh23 = __floats2half2_rn(xv.z, xv.w);
        float2 xf01 = __half22float2(xh01), xf23 = __half22float2(xh23);
        __half2 xl01 = __floats2half2_rn(xv.x - xf01.x, xv.y - xf01.y);
        __half2 xl23 = __floats2half2_rn(xv.z - xf23.x, xv.w - xf23.y);
        *(uint2*)(sm + GX_HI + off) = make_uint2(h2u(xh01), h2u(xh23));
        *(uint2*)(sm + GX_LO + off) = make_uint2(h2u(xl01), h2u(xl23));
        float4 wv = *(const float4*)(W + (size_t)row * FF + f4 * 4);
        __half2 wh01 = __floats2half2_rn(wv.x, wv.y);
        __half2 wh23 = __floats2half2_rn(wv.z, wv.w);
        float2 wf01 = __half22float2(wh01), wf23 = __half22float2(wh23);
        __half2 wl01 = __floats2half2_rn(wv.x - wf01.x, wv.y - wf01.y);
        __half2 wl23 = __floats2half2_rn(wv.z - wf23.x, wv.w - wf23.y);
        *(uint2*)(sm + GW_HI + off) = make_uint2(h2u(wh01), h2u(wh23));
        *(uint2*)(sm + GW_LO + off) = make_uint2(h2u(wl01), h2u(wl23));
    }
    __syncthreads();

    int mwarp = (wid >> 2) * 64;
    int nwarp = (wid & 3) * 32;
    uint32_t axhi = sb + GX_HI + (uint32_t)(mwarp + (lane & 15)) * GSTR + (lane >> 4) * 16;
    uint32_t axlo = axhi + (GX_LO - GX_HI);
    uint32_t bwhi = sb + GW_HI +
        (uint32_t)(nwarp + (lane & 7) + ((lane >> 4) & 1) * 8) * GSTR +
        ((lane >> 3) & 1) * 16;
    uint32_t bwlo = bwhi + (GW_LO - GW_HI);

    float acc[4][4][4];
    #pragma unroll
    for (int mi = 0; mi < 4; mi++)
        #pragma unroll
        for (int n8 = 0; n8 < 4; n8++)
            #pragma unroll
            for (int x = 0; x < 4; x++) acc[mi][n8][x] = 0.f;

    #pragma unroll
    for (int kk = 0; kk < 8; kk++) {
        uint32_t ah[4][4], al[4][4];
        #pragma unroll
        for (int mi = 0; mi < 4; mi++) {
            ldsm_x4(ah[mi], axhi + mi * 16 * GSTR + kk * 32);
            ldsm_x4(al[mi], axlo + mi * 16 * GSTR + kk * 32);
        }
        #pragma unroll
        for (int nb = 0; nb < 2; nb++) {
            uint32_t bh[4], bl[4];
            ldsm_x4(bh, bwhi + nb * 16 * GSTR + kk * 32);
            ldsm_x4(bl, bwlo + nb * 16 * GSTR + kk * 32);
            #pragma unroll
            for (int mi = 0; mi < 4; mi++) {
                mma16816(acc[mi][nb * 2 + 0], ah[mi], bh + 0);
                mma16816(acc[mi][nb * 2 + 1], ah[mi], bh + 2);
                mma16816(acc[mi][nb * 2 + 0], al[mi], bh + 0);
                mma16816(acc[mi][nb * 2 + 1], al[mi], bh + 2);
                mma16816(acc[mi][nb * 2 + 0], ah[mi], bl + 0);
                mma16816(acc[mi][nb * 2 + 1], ah[mi], bl + 2);
            }
        }
    }

    #pragma unroll
    for (int mi = 0; mi < 4; mi++) {
        int r0 = mwarp + mi * 16 + (lane >> 2);
        #pragma unroll
        for (int n8 = 0; n8 < 4; n8++) {
            int col = nwarp + n8 * 8 + (lane & 3) * 2;
            float b0 = __ldg(bias + col), b1 = __ldg(bias + col + 1);
            __half2 o0 = __floats2half2_rn(acc[mi][n8][0] + b0, acc[mi][n8][1] + b1);
            __half2 o1 = __floats2half2_rn(acc[mi][n8][2] + b0, acc[mi][n8][3] + b1);
            *(uint32_t*)(outh + (size_t)(i0 + r0) * FF + col) = h2u(o0);
            *(uint32_t*)(outh + (size_t)(i0 + r0 + 8) * FF + col) = h2u(o1);
        }
    }
}

// ---------------- kernel 3b: convert Wo to fp16 hi/lo ----------------
__global__ void k_wo(const float* __restrict__ Wo) {
    int t = threadIdx.x;
    #pragma unroll
    for (int kk = 0; kk < 16; kk++) {
        int e = t + kk * 256;
        float4 w = ((const float4*)Wo)[e];
        __half2 h01 = __floats2half2_rn(w.x, w.y);
        __half2 h23 = __floats2half2_rn(w.z, w.w);
        float2 f01 = __half22float2(h01), f23 = __half22float2(h23);
        __half2 l01 = __floats2half2_rn(w.x - f01.x, w.y - f01.y);
        __half2 l23 = __floats2half2_rn(w.z - f23.x, w.w - f23.y);
        *(uint2*)(g_woh + (size_t)e * 4) = make_uint2(h2u(h01), h2u(h23));
        *(uint2*)(g_wol + (size_t)e * 4) = make_uint2(h2u(l01), h2u(l23));
    }
}

// ---------------- kernel 4: warp-specialized attn (raw adj) + fused Wo -----
// 512 threads: warps 0-7 consumers (MMA), 8-15 producers (adj LDG, P-gen, V cp).
// 4-stage ring: [P 18432][V 17408]; full barriers 1-4, empty 5-8.
#define PSTRIDE 144
#define VSTRIDE 272
#define STAGE   35840
#define VOFF    18432
#define NSTG    4
#define E2_OFF  143360       // 32768
#define RS_OFF  176128       // 1024
#define IV_OFF  177152       // 512
#define SM_TOTAL 177664
#define ESTR 272
#define NCH (NN / KC)        // 64

__global__ void __launch_bounds__(512, 1)
k_attn_mma(const int* __restrict__ adj, float* __restrict__ out) {
    extern __shared__ char sm[];
    int t = threadIdx.x;
    int lane = t & 31, wid = t >> 5;
    int role = wid >> 3;
    int w8 = wid & 7;
    int t256 = t & 255;
    int b = blockIdx.y;
    int it0 = blockIdx.x * 128;

    uint32_t sbase = smem_u32(sm);

    // stage e2 pairs for this batch
    {
        float4* d = (float4*)(sm + E2_OFF);
        const float4* s = (const float4*)(g_e2 + b * NN);
        #pragma unroll
        for (int kk = 0; kk < 4; kk++) d[t + kk * 512] = s[t + kk * 512];
    }
    __syncthreads();

    if (role == 1) {
        // ================= PRODUCER =================
        int prow = t256 >> 1;
        int jh = (t256 & 1) * 32;
        float2 e1 = g_e1[b * NN + it0 + prow];
        float ea = e1.x, ea2 = e1.y;
        const int4* adjr = (const int4*)(adj + (size_t)(b * NN + it0 + prow) * NN + jh);
        const __half* vph = g_vph + (size_t)b * NN * FF;
        char* pdstH = sm + prow * PSTRIDE + jh * 2;
        const float4* e2q = (const float4*)(sm + E2_OFF) + (t256 & 1) * 16;
        int vr = t256 >> 2, vs = t256 & 3;
        uint32_t vdst = sbase + VOFF + vr * VSTRIDE + vs * 64;
        const __half* vsrc0 = vph + (size_t)vr * FF + vs * 32;

        float rs = 0.f;

        // prefetch chunk 0 masks (8 x int4 = 32 ints)
        int4 am[8];
        #pragma unroll
        for (int q = 0; q < 8; q++) am[q] = __ldg(adjr + q);

        for (int c = 0; c < NCH; c++) {
            int s = c & 3;
            if (c >= NSTG) BARS(5 + s);
            // V cp.async for chunk c
            {
                const __half* src = vsrc0 + (size_t)c * KC * FF;
                uint32_t d = vdst + s * STAGE;
                #pragma unroll
                for (int kk = 0; kk < 4; kk++)
                    cp16(d + kk * 16, src + kk * 8);
                CP_COMMIT();
            }
            // P gen from register masks
            {
                char* dh = pdstH + s * STAGE;
                #pragma unroll
                for (int qq = 0; qq < 8; qq++) {
                    float4 A  = e2q[c * 32 + qq * 2];
                    float4 Bq = e2q[c * 32 + qq * 2 + 1];
                    int4 m = am[qq];
                    float p0 = (m.x > 0) ? fmaxf(ea * A.x,  ea2 * A.y)  : 0.f;
                    float p1 = (m.y > 0) ? fmaxf(ea * A.z,  ea2 * A.w)  : 0.f;
                    float p2 = (m.z > 0) ? fmaxf(ea * Bq.x, ea2 * Bq.y) : 0.f;
                    float p3 = (m.w > 0) ? fmaxf(ea * Bq.z, ea2 * Bq.w) : 0.f;
                    rs += (p0 + p1) + (p2 + p3);
                    __half2 h01 = __floats2half2_rn(p0, p1);
                    __half2 h23 = __floats2half2_rn(p2, p3);
                    *(uint2*)(dh + qq * 8) = make_uint2(h2u(h01), h2u(h23));
                }
            }
            // prefetch next chunk's masks
            if (c + 1 < NCH) {
                const int4* nxt = adjr + (c + 1) * (KC / 4);
                #pragma unroll
                for (int q = 0; q < 8; q++) am[q] = __ldg(nxt + q);
            }
            // deferred arrive: chunk c-1's V is complete once <=1 group outstanding
            if (c > 0) {
                CP_WAIT1();
                BARA(1 + ((c - 1) & 3));
            }
        }
        CP_WAIT0();
        BARA(1 + ((NCH - 1) & 3));

        ((float*)(sm + RS_OFF))[t256] = rs;
        __syncthreads();              // (A)
        // stage Wo hi/lo into [69632..139264)
        #pragma unroll
        for (int kk = 0; kk < 8; kk++) {
            int id = t256 + kk * 256;
            int row = id >> 4, cc = id & 15;
            cp16(sbase + 69632 + row * ESTR + cc * 16, g_woh + (size_t)row * FF + cc * 8);
            cp16(sbase + 104448 + row * ESTR + cc * 16, g_wol + (size_t)row * FF + cc * 8);
        }
        CP_COMMIT();
        CP_WAIT0();
        __syncthreads();              // (B)
    } else {
        // ================= CONSUMER =================
        int mwarp = (w8 >> 2) * 64;
        int nwarp = (w8 & 3) * 32;
        uint32_t aoff = sbase + (uint32_t)(mwarp + (lane & 15)) * PSTRIDE + (lane >> 4) * 16;
        uint32_t boff = sbase + VOFF + (uint32_t)(lane & 15) * VSTRIDE + (nwarp + (lane >> 4) * 8) * 2;

        float acc[4][4][4];
        #pragma unroll
        for (int mi = 0; mi < 4; mi++)
            #pragma unroll
            for (int n8 = 0; n8 < 4; n8++)
                #pragma unroll
                for (int x = 0; x < 4; x++) acc[mi][n8][x] = 0.f;

        for (int c = 0; c < NCH; c++) {
            int s = c & 3;
            BARS(1 + s);
            uint32_t pb = aoff + s * STAGE;
            uint32_t vb = boff + s * STAGE;
            #pragma unroll
            for (int kk = 0; kk < 4; kk++) {
                uint32_t ah[4][4];
                #pragma unroll
                for (int mi = 0; mi < 4; mi++)
                    ldsm_x4(ah[mi], pb + mi * 16 * PSTRIDE + kk * 32);
                #pragma unroll
                for (int nb = 0; nb < 2; nb++) {
                    uint32_t bh[4];
                    ldsm_x4_t(bh, vb + kk * 16 * VSTRIDE + nb * 32);
                    #pragma unroll
                    for (int mi = 0; mi < 4; mi++) {
                        mma16816(acc[mi][nb * 2 + 0], ah[mi], bh + 0);
                        mma16816(acc[mi][nb * 2 + 1], ah[mi], bh + 2);
                    }
                }
            }
            if (c + NSTG < NCH) BARA(5 + s);
        }
        __syncthreads();              // (A)
        // per-thread inverse normalizers from rs partials
        float invr[8];
        {
            const float* rss = (const float*)(sm + RS_OFF);
            #pragma unroll
            for (int mi = 0; mi < 4; mi++) {
                int r0 = (w8 >> 2) * 64 + mi * 16 + (lane >> 2);
                invr[mi * 2 + 0] = 1.0f / (rss[2 * r0] + rss[2 * r0 + 1]);
                invr[mi * 2 + 1] = 1.0f / (rss[2 * (r0 + 8)] + rss[2 * (r0 + 8) + 1]);
            }
        }
        int mwarp2 = (w8 >> 2) * 64, nwarp2 = (w8 & 3) * 32;
        #pragma unroll
        for (int mi = 0; mi < 4; mi++) {
            int r0 = mwarp2 + mi * 16 + (lane >> 2);
            float iv0 = invr[mi * 2 + 0], iv1 = invr[mi * 2 + 1];
            #pragma unroll
            for (int n8 = 0; n8 < 4; n8++) {
                int col = nwarp2 + n8 * 8 + (lane & 3) * 2;
                float h00 = acc[mi][n8][0] * iv0, h01v = acc[mi][n8][1] * iv0;
                float h10 = acc[mi][n8][2] * iv1, h11 = acc[mi][n8][3] * iv1;
                __half2 hh0 = __floats2half2_rn(h00, h01v);
                __half2 hh1 = __floats2half2_rn(h10, h11);
                float2 hf0 = __half22float2(hh0), hf1 = __half22float2(hh1);
                __half2 hl0 = __floats2half2_rn(h00 - hf0.x, h01v - hf0.y);
                __half2 hl1 = __floats2half2_rn(h10 - hf1.x, h11 - hf1.y);
                *(uint32_t*)(sm + r0 * ESTR + col * 2) = h2u(hh0);
                *(uint32_t*)(sm + (r0 + 8) * ESTR + col * 2) = h2u(hh1);
                *(uint32_t*)(sm + 34816 + r0 * ESTR + col * 2) = h2u(hl0);
                *(uint32_t*)(sm + 34816 + (r0 + 8) * ESTR + col * 2) = h2u(hl1);
            }
        }
        __syncthreads();              // (B)
    }

    // ======== fused output projection: all 16 warps ========
    {
        int em = (wid >> 2) * 32;
        int en = (wid & 3) * 32;
        uint32_t ahh = sbase + (uint32_t)(em + (lane & 15)) * ESTR + (lane >> 4) * 16;
        uint32_t ahl = ahh + 34816;
        uint32_t bwh = sbase + 69632 +
            (uint32_t)(en + (lane & 7) + ((lane >> 4) & 1) * 8) * ESTR +
            ((lane >> 3) & 1) * 16;
        uint32_t bwl = bwh + 34816;

        float o2[2][4][4];
        #pragma unroll
        for (int mi = 0; mi < 2; mi++)
            #pragma unroll
            for (int n8 = 0; n8 < 4; n8++)
                #pragma unroll
                for (int x = 0; x < 4; x++) o2[mi][n8][x] = 0.f;

        #pragma unroll
        for (int kk = 0; kk < 8; kk++) {
            uint32_t ah[2][4], al[2][4];
            #pragma unroll
            for (int mi = 0; mi < 2; mi++) {
                ldsm_x4(ah[mi], ahh + mi * 16 * ESTR + kk * 32);
                ldsm_x4(al[mi], ahl + mi * 16 * ESTR + kk * 32);
            }
            #pragma unroll
            for (int nb = 0; nb < 2; nb++) {
                uint32_t bh[4], bl[4];
                ldsm_x4(bh, bwh + nb * 16 * ESTR + kk * 32);
                ldsm_x4(bl, bwl + nb * 16 * ESTR + kk * 32);
                #pragma unroll
                for (int mi = 0; mi < 2; mi++) {
                    mma16816(o2[mi][nb * 2 + 0], ah[mi], bh + 0);
                    mma16816(o2[mi][nb * 2 + 1], ah[mi], bh + 2);
                    mma16816(o2[mi][nb * 2 + 0], al[mi], bh + 0);
                    mma16816(o2[mi][nb * 2 + 1], al[mi], bh + 2);
                    mma16816(o2[mi][nb * 2 + 0], ah[mi], bl + 0);
                    mma16816(o2[mi][nb * 2 + 1], ah[mi], bl + 2);
                }
            }
        }

        #pragma unroll
        for (int mi = 0; mi < 2; mi++) {
            int r0 = em + mi * 16 + (lane >> 2);
            #pragma unroll
            for (int n8 = 0; n8 < 4; n8++) {
                int col = en + n8 * 8 + (lane & 3) * 2;
                float2 v0 = make_float2(leaky(o2[mi][n8][0]), leaky(o2[mi][n8][1]));
                float2 v1 = make_float2(leaky(o2[mi][n8][2]), leaky(o2[mi][n8][3]));
                *(float2*)(out + (size_t)(b * NN + it0 + r0) * FF + col) = v0;
                *(float2*)(out + (size_t)(b * NN + it0 + r0 + 8) * FF + col) = v1;
            }
        }
    }
}

// ---------------- launch ----------------
extern "C" void kernel_launch(void* const* d_in, const int* in_sizes, int n_in,
                              void* d_out, int out_size) {
    const float* q    = (const float*)d_in[0];
    const float* k    = (const float*)d_in[1];
    const float* v    = (const float*)d_in[2];
    const int*   adj  = (const int*)  d_in[3];
    const float* Wq_w = (const float*)d_in[4];
    const float* Wq_b = (const float*)d_in[5];
    const float* Wk_w = (const float*)d_in[6];
    const float* Wk_b = (const float*)d_in[7];
    const float* Wv_w = (const float*)d_in[8];
    const float* Wv_b = (const float*)d_in[9];
    const float* a    = (const float*)d_in[10];
    const float* Wo_w = (const float*)d_in[11];
    float* out = (float*)d_out;

    void* vph_ptr = nullptr;
    cudaGetSymbolAddress(&vph_ptr, g_vph);

    cudaFuncSetAttribute(k_attn_mma, cudaFuncAttributeMaxDynamicSharedMemorySize, SM_TOTAL);
    cudaFuncSetAttribute(k_gemm_tc, cudaFuncAttributeMaxDynamicSharedMemorySize, G_TOTAL);

    k_prep<<<1, 128>>>(Wq_w, Wq_b, Wk_w, Wk_b, a);
    k_wh<<<(2 * BB * NN) / 8, 256>>>(q, k);
    k_gemm_tc<<<BB * NN / 128, 256, G_TOTAL>>>(v, Wv_w, Wv_b, (__half*)vph_ptr);
    k_wo<<<1, 256>>>(Wo_w);

    {
        dim3 grid(NN / 128, BB);
        k_attn_mma<<<grid, 512, SM_TOTAL>>>(adj, out);
    }
}

// round 16
// speedup vs baseline: 1.2855x; 1.2855x over previous
#include <cuda_runtime.h>
#include <cuda_fp16.h>
#include <cstdint>

#define BB 4
#define NN 4096
#define FF 128
#define ALPHA 0.1f
#define KC 64

// ---------------- device scratch ----------------
__device__ float g_w1[FF], g_w2[FF], g_c[2];
__device__ __align__(16) float2 g_e1[BB * NN];
__device__ __align__(16) float2 g_e2[BB * NN];
__device__ __align__(16) __half g_vph[BB * NN * FF];            // fp16 [b][j][f]
__device__ __align__(16) __half g_woh[FF * FF];
__device__ __align__(16) __half g_wol[FF * FF];
__device__ __align__(16) uint32_t g_adjbits[BB * NN * (NN/32)];

__device__ __forceinline__ float leaky(float x) { return fmaxf(x, ALPHA * x); }

// ---------------- mma.sync helpers ----------------
__device__ __forceinline__ void mma16816(float* d, const uint32_t* a, const uint32_t* b) {
    asm volatile("mma.sync.aligned.m16n8k16.row.col.f32.f16.f16.f32 "
        "{%0,%1,%2,%3},{%4,%5,%6,%7},{%8,%9},{%0,%1,%2,%3};"
        : "+f"(d[0]), "+f"(d[1]), "+f"(d[2]), "+f"(d[3])
        : "r"(a[0]), "r"(a[1]), "r"(a[2]), "r"(a[3]), "r"(b[0]), "r"(b[1]));
}
__device__ __forceinline__ void ldsm_x4(uint32_t* r, uint32_t addr) {
    asm volatile("ldmatrix.sync.aligned.m8n8.x4.shared.b16 {%0,%1,%2,%3},[%4];"
        : "=r"(r[0]), "=r"(r[1]), "=r"(r[2]), "=r"(r[3]) : "r"(addr));
}
__device__ __forceinline__ void ldsm_x4_t(uint32_t* r, uint32_t addr) {
    asm volatile("ldmatrix.sync.aligned.m8n8.x4.trans.shared.b16 {%0,%1,%2,%3},[%4];"
        : "=r"(r[0]), "=r"(r[1]), "=r"(r[2]), "=r"(r[3]) : "r"(addr));
}
__device__ __forceinline__ uint32_t smem_u32(const void* p) {
    uint32_t a;
    asm("{ .reg .u64 t; cvta.to.shared.u64 t, %1; cvt.u32.u64 %0, t; }" : "=r"(a) : "l"(p));
    return a;
}
__device__ __forceinline__ void cp16(uint32_t dst, const void* src) {
    asm volatile("cp.async.cg.shared.global [%0], [%1], 16;" :: "r"(dst), "l"(src) : "memory");
}
#define CP_COMMIT() asm volatile("cp.async.commit_group;" ::: "memory")
#define CP_WAIT0()  asm volatile("cp.async.wait_group 0;" ::: "memory")
#define CP_WAIT1()  asm volatile("cp.async.wait_group 1;" ::: "memory")
#define BARS(id)    asm volatile("bar.sync %0, 512;"   :: "r"(id) : "memory")
#define BARA(id)    asm volatile("bar.arrive %0, 512;" :: "r"(id) : "memory")
__device__ __forceinline__ uint32_t h2u(__half2 h) { return *(uint32_t*)&h; }

// ---------------- kernel 0: pack adj into bitmask ----------------
__global__ void __launch_bounds__(256) k_pack(const int* __restrict__ adj) {
    int t = blockIdx.x * 256 + threadIdx.x;
    const int4* p = (const int4*)adj + (size_t)t * 2;
    int4 a = p[0], b = p[1];
    uint32_t bits =
        (uint32_t)(a.x != 0)        | ((uint32_t)(a.y != 0) << 1) |
        ((uint32_t)(a.z != 0) << 2) | ((uint32_t)(a.w != 0) << 3) |
        ((uint32_t)(b.x != 0) << 4) | ((uint32_t)(b.y != 0) << 5) |
        ((uint32_t)(b.z != 0) << 6) | ((uint32_t)(b.w != 0) << 7);
    int lane = threadIdx.x & 31;
    uint32_t my = bits << ((lane & 3) * 8);
    my |= __shfl_xor_sync(0xffffffffu, my, 1);
    my |= __shfl_xor_sync(0xffffffffu, my, 2);
    if ((lane & 3) == 0) g_adjbits[t >> 2] = my;
}

// ---------------- kernel 1: fold a into Q/K projections ----------------
__global__ void k_prep(const float* __restrict__ Wq_w, const float* __restrict__ Wq_b,
                       const float* __restrict__ Wk_w, const float* __restrict__ Wk_b,
                       const float* __restrict__ a) {
    int f = threadIdx.x;
    float s1 = 0.f, s2 = 0.f;
    for (int o = 0; o < FF; o++) {
        s1 += Wq_w[o * FF + f] * a[o];
        s2 += Wk_w[o * FF + f] * a[FF + o];
    }
    g_w1[f] = s1; g_w2[f] = s2;
    if (f == 0) {
        float c1 = 0.f, c2 = 0.f;
        for (int o = 0; o < FF; o++) { c1 += Wq_b[o] * a[o]; c2 += Wk_b[o] * a[FF + o]; }
        g_c[0] = c1; g_c[1] = c2;
    }
}

// ---------------- kernel 2: Wh -> (exp(wh), exp(0.1 wh)) pairs -------------
__global__ void k_wh(const float* __restrict__ q, const float* __restrict__ k) {
    int warp = threadIdx.x >> 5, lane = threadIdx.x & 31;
    int row = blockIdx.x * 8 + warp;
    const float* src; const float* w; float c; float2* dst; int r;
    if (row < BB * NN) { src = q; w = g_w1; c = g_c[0]; dst = g_e1; r = row; }
    else               { src = k; w = g_w2; c = g_c[1]; dst = g_e2; r = row - BB * NN; }
    float4 x  = ((const float4*)(src + (size_t)r * FF))[lane];
    float4 ww = ((const float4*)w)[lane];
    float s = x.x * ww.x + x.y * ww.y + x.z * ww.z + x.w * ww.w;
    #pragma unroll
    for (int o = 16; o > 0; o >>= 1) s += __shfl_xor_sync(0xffffffffu, s, o);
    if (lane == 0) {
        float wh = s + c;
        dst[r] = make_float2(__expf(wh), __expf(ALPHA * wh));
    }
}

// ---------------- kernel 3: V projection, tensor core ----------------------
#define GSTR 272
#define GX_HI 0
#define GX_LO 34816
#define GW_HI 69632
#define GW_LO 104448
#define G_TOTAL 139264

__global__ void __launch_bounds__(256, 1)
k_gemm_tc(const float* __restrict__ in, const float* __restrict__ W,
          const float* __restrict__ bias, __half* __restrict__ outh) {
    extern __shared__ char sm[];
    int t = threadIdx.x, lane = t & 31, wid = t >> 5;
    int i0 = blockIdx.x * 128;
    uint32_t sb = smem_u32(sm);

    #pragma unroll
    for (int kk = 0; kk < 16; kk++) {
        int e = t + kk * 256;
        int row = e >> 5, f4 = e & 31;
        int off = row * GSTR + f4 * 8;
        float4 xv = *(const float4*)(in + (size_t)(i0 + row) * FF + f4 * 4);
        __half2 xh01 = __floats2half2_rn(xv.x, xv.y);
        __half2 xh23 = __floats2half2_rn(xv.z, xv.w);
        float2 xf01 = __half22float2(xh01), xf23 = __half22float2(xh23);
        __half2 xl01 = __floats2half2_rn(xv.x - xf01.x, xv.y - xf01.y);
        __half2 xl23 = __floats2half2_rn(xv.z - xf23.x, xv.w - xf23.y);
        *(uint2*)(sm + GX_HI + off) = make_uint2(h2u(xh01), h2u(xh23));
        *(uint2*)(sm + GX_LO + off) = make_uint2(h2u(xl01), h2u(xl23));
        float4 wv = *(const float4*)(W + (size_t)row * FF + f4 * 4);
        __half2 wh01 = __floats2half2_rn(wv.x, wv.y);
        __half2 wh23 = __floats2half2_rn(wv.z, wv.w);
        float2 wf01 = __half22float2(wh01), wf23 = __half22float2(wh23);
        __half2 wl01 = __floats2half2_rn(wv.x - wf01.x, wv.y - wf01.y);
        __half2 wl23 = __floats2half2_rn(wv.z - wf23.x, wv.w - wf23.y);
        *(uint2*)(sm + GW_HI + off) = make_uint2(h2u(wh01), h2u(wh23));
        *(uint2*)(sm + GW_LO + off) = make_uint2(h2u(wl01), h2u(wl23));
    }
    __syncthreads();

    int mwarp = (wid >> 2) * 64;
    int nwarp = (wid & 3) * 32;
    uint32_t axhi = sb + GX_HI + (uint32_t)(mwarp + (lane & 15)) * GSTR + (lane >> 4) * 16;
    uint32_t axlo = axhi + (GX_LO - GX_HI);
    uint32_t bwhi = sb + GW_HI +
        (uint32_t)(nwarp + (lane & 7) + ((lane >> 4) & 1) * 8) * GSTR +
        ((lane >> 3) & 1) * 16;
    uint32_t bwlo = bwhi + (GW_LO - GW_HI);

    float acc[4][4][4];
    #pragma unroll
    for (int mi = 0; mi < 4; mi++)
        #pragma unroll
        for (int n8 = 0; n8 < 4; n8++)
            #pragma unroll
            for (int x = 0; x < 4; x++) acc[mi][n8][x] = 0.f;

    #pragma unroll
    for (int kk = 0; kk < 8; kk++) {
        uint32_t ah[4][4], al[4][4];
        #pragma unroll
        for (int mi = 0; mi < 4; mi++) {
            ldsm_x4(ah[mi], axhi + mi * 16 * GSTR + kk * 32);
            ldsm_x4(al[mi], axlo + mi * 16 * GSTR + kk * 32);
        }
        #pragma unroll
        for (int nb = 0; nb < 2; nb++) {
            uint32_t bh[4], bl[4];
            ldsm_x4(bh, bwhi + nb * 16 * GSTR + kk * 32);
            ldsm_x4(bl, bwlo + nb * 16 * GSTR + kk * 32);
            #pragma unroll
            for (int mi = 0; mi < 4; mi++) {
                mma16816(acc[mi][nb * 2 + 0], ah[mi], bh + 0);
                mma16816(acc[mi][nb * 2 + 1], ah[mi], bh + 2);
                mma16816(acc[mi][nb * 2 + 0], al[mi], bh + 0);
                mma16816(acc[mi][nb * 2 + 1], al[mi], bh + 2);
                mma16816(acc[mi][nb * 2 + 0], ah[mi], bl + 0);
                mma16816(acc[mi][nb * 2 + 1], ah[mi], bl + 2);
            }
        }
    }

    #pragma unroll
    for (int mi = 0; mi < 4; mi++) {
        int r0 = mwarp + mi * 16 + (lane >> 2);
        #pragma unroll
        for (int n8 = 0; n8 < 4; n8++) {
            int col = nwarp + n8 * 8 + (lane & 3) * 2;
            float b0 = __ldg(bias + col), b1 = __ldg(bias + col + 1);
            __half2 o0 = __floats2half2_rn(acc[mi][n8][0] + b0, acc[mi][n8][1] + b1);
            __half2 o1 = __floats2half2_rn(acc[mi][n8][2] + b0, acc[mi][n8][3] + b1);
            *(uint32_t*)(outh + (size_t)(i0 + r0) * FF + col) = h2u(o0);
            *(uint32_t*)(outh + (size_t)(i0 + r0 + 8) * FF + col) = h2u(o1);
        }
    }
}

// ---------------- kernel 3b: convert Wo to fp16 hi/lo ----------------
__global__ void k_wo(const float* __restrict__ Wo) {
    int t = threadIdx.x;
    #pragma unroll
    for (int kk = 0; kk < 16; kk++) {
        int e = t + kk * 256;
        float4 w = ((const float4*)Wo)[e];
        __half2 h01 = __floats2half2_rn(w.x, w.y);
        __half2 h23 = __floats2half2_rn(w.z, w.w);
        float2 f01 = __half22float2(h01), f23 = __half22float2(h23);
        __half2 l01 = __floats2half2_rn(w.x - f01.x, w.y - f01.y);
        __half2 l23 = __floats2half2_rn(w.z - f23.x, w.w - f23.y);
        *(uint2*)(g_woh + (size_t)e * 4) = make_uint2(h2u(h01), h2u(h23));
        *(uint2*)(g_wol + (size_t)e * 4) = make_uint2(h2u(l01), h2u(l23));
    }
}

// ---------------- kernel 4: warp-specialized attn + fused output proj ------
// 512 threads: warps 0-7 consumers (MMA), 8-15 producers (mask, P-gen, V cp).
// 4-stage ring: [P 18432][V 17408]; full barriers 1-4, empty 5-8.
#define PSTRIDE 144
#define VSTRIDE 272
#define STAGE   35840
#define VOFF    18432
#define NSTG    4
#define E2_OFF  143360       // 32768
#define RS_OFF  176128       // 1024
#define IV_OFF  177152       // 512
#define SM_TOTAL 177664
#define ESTR 272
#define NCH (NN / KC)        // 64

__global__ void __launch_bounds__(512, 1)
k_attn_mma(float* __restrict__ out) {
    extern __shared__ char sm[];
    int t = threadIdx.x;
    int lane = t & 31, wid = t >> 5;
    int role = wid >> 3;
    int w8 = wid & 7;
    int t256 = t & 255;
    int b = blockIdx.y;
    int it0 = blockIdx.x * 128;

    uint32_t sbase = smem_u32(sm);

    // stage e2 pairs for this batch
    {
        float4* d = (float4*)(sm + E2_OFF);
        const float4* s = (const float4*)(g_e2 + b * NN);
        #pragma unroll
        for (int kk = 0; kk < 4; kk++) d[t + kk * 512] = s[t + kk * 512];
    }
    __syncthreads();

    if (role == 1) {
        // ================= PRODUCER =================
        int prow = t256 >> 1;
        int jh = (t256 & 1) * 32;
        float2 e1 = g_e1[b * NN + it0 + prow];
        float ea = e1.x, ea2 = e1.y;
        const uint32_t* maskp = g_adjbits + (size_t)(b * NN + it0 + prow) * (NN / 32) + (t256 & 1);
        const __half* vph = g_vph + (size_t)b * NN * FF;
        char* pdstH = sm + prow * PSTRIDE + jh * 2;
        const float4* e2q = (const float4*)(sm + E2_OFF) + (t256 & 1) * 16;
        int vr = t256 >> 2, vs = t256 & 3;
        uint32_t vdst = sbase + VOFF + vr * VSTRIDE + vs * 64;
        const __half* vsrc0 = vph + (size_t)vr * FF + vs * 32;

        float rs = 0.f;
        uint2 hiR[8];
        uint32_t mNext = __ldg(maskp);

        for (int c = 0; c < NCH; c++) {
            int s = c & 3;
            uint32_t m = mNext;
            if (c + 1 < NCH) mNext = __ldg(maskp + 2 * (c + 1));
            if (c >= NSTG) BARS(5 + s);
            // V cp.async for chunk c (completion deferred one chunk)
            {
                const __half* src = vsrc0 + (size_t)c * KC * FF;
                uint32_t d = vdst + s * STAGE;
                #pragma unroll
                for (int kk = 0; kk < 4; kk++)
                    cp16(d + kk * 16, src + kk * 8);
                CP_COMMIT();
            }
            // P gen
            #pragma unroll
            for (int qq = 0; qq < 8; qq++) {
                float4 A  = e2q[c * 32 + qq * 2];
                float4 Bq = e2q[c * 32 + qq * 2 + 1];
                float p0 = (m >> (qq * 4 + 0)) & 1u ? fmaxf(ea * A.x,  ea2 * A.y)  : 0.f;
                float p1 = (m >> (qq * 4 + 1)) & 1u ? fmaxf(ea * A.z,  ea2 * A.w)  : 0.f;
                float p2 = (m >> (qq * 4 + 2)) & 1u ? fmaxf(ea * Bq.x, ea2 * Bq.y) : 0.f;
                float p3 = (m >> (qq * 4 + 3)) & 1u ? fmaxf(ea * Bq.z, ea2 * Bq.w) : 0.f;
                rs += (p0 + p1) + (p2 + p3);
                __half2 h01 = __floats2half2_rn(p0, p1);
                __half2 h23 = __floats2half2_rn(p2, p3);
                hiR[qq] = make_uint2(h2u(h01), h2u(h23));
            }
            {
                char* dh = pdstH + s * STAGE;
                #pragma unroll
                for (int qq = 0; qq < 8; qq++)
                    *(uint2*)(dh + qq * 8) = hiR[qq];
            }
            // deferred arrive for chunk c-1 (its V group is now <=1 outstanding)
            if (c > 0) {
                CP_WAIT1();
                BARA(1 + ((c - 1) & 3));
            }
        }
        CP_WAIT0();
        BARA(1 + ((NCH - 1) & 3));

        ((float*)(sm + RS_OFF))[t256] = rs;
        __syncthreads();              // (A)
        // stage Wo hi/lo into [69632..139264)
        #pragma unroll
        for (int kk = 0; kk < 8; kk++) {
            int id = t256 + kk * 256;
            int row = id >> 4, cc = id & 15;
            cp16(sbase + 69632 + row * ESTR + cc * 16, g_woh + (size_t)row * FF + cc * 8);
            cp16(sbase + 104448 + row * ESTR + cc * 16, g_wol + (size_t)row * FF + cc * 8);
        }
        CP_COMMIT();
        CP_WAIT0();
        __syncthreads();              // (B)
    } else {
        // ================= CONSUMER =================
        int mwarp = (w8 >> 2) * 64;
        int nwarp = (w8 & 3) * 32;
        uint32_t aoff = sbase + (uint32_t)(mwarp + (lane & 15)) * PSTRIDE + (lane >> 4) * 16;
        uint32_t boff = sbase + VOFF + (uint32_t)(lane & 15) * VSTRIDE + (nwarp + (lane >> 4) * 8) * 2;

        float acc[4][4][4];
        #pragma unroll
        for (int mi = 0; mi < 4; mi++)
            #pragma unroll
            for (int n8 = 0; n8 < 4; n8++)
                #pragma unroll
                for (int x = 0; x < 4; x++) acc[mi][n8][x] = 0.f;

        for (int c = 0; c < NCH; c++) {
            int s = c & 3;
            BARS(1 + s);
            uint32_t pb = aoff + s * STAGE;
            uint32_t vb = boff + s * STAGE;
            #pragma unroll
            for (int kk = 0; kk < 4; kk++) {
                uint32_t ah[4][4];
                #pragma unroll
                for (int mi = 0; mi < 4; mi++)
                    ldsm_x4(ah[mi], pb + mi * 16 * PSTRIDE + kk * 32);
                #pragma unroll
                for (int nb = 0; nb < 2; nb++) {
                    uint32_t bh[4];
                    ldsm_x4_t(bh, vb + kk * 16 * VSTRIDE + nb * 32);
                    #pragma unroll
                    for (int mi = 0; mi < 4; mi++) {
                        mma16816(acc[mi][nb * 2 + 0], ah[mi], bh + 0);
                        mma16816(acc[mi][nb * 2 + 1], ah[mi], bh + 2);
                    }
                }
            }
            if (c + NSTG < NCH) BARA(5 + s);
        }
        __syncthreads();              // (A)
        float invr[8];
        {
            const float* rss = (const float*)(sm + RS_OFF);
            #pragma unroll
            for (int mi = 0; mi < 4; mi++) {
                int r0 = (w8 >> 2) * 64 + mi * 16 + (lane >> 2);
                invr[mi * 2 + 0] = 1.0f / (rss[2 * r0] + rss[2 * r0 + 1]);
                invr[mi * 2 + 1] = 1.0f / (rss[2 * (r0 + 8)] + rss[2 * (r0 + 8) + 1]);
            }
        }
        int mwarp2 = (w8 >> 2) * 64, nwarp2 = (w8 & 3) * 32;
        #pragma unroll
        for (int mi = 0; mi < 4; mi++) {
            int r0 = mwarp2 + mi * 16 + (lane >> 2);
            float iv0 = invr[mi * 2 + 0], iv1 = invr[mi * 2 + 1];
            #pragma unroll
            for (int n8 = 0; n8 < 4; n8++) {
                int col = nwarp2 + n8 * 8 + (lane & 3) * 2;
                float h00 = acc[mi][n8][0] * iv0, h01v = acc[mi][n8][1] * iv0;
                float h10 = acc[mi][n8][2] * iv1, h11 = acc[mi][n8][3] * iv1;
                __half2 hh0 = __floats2half2_rn(h00, h01v);
                __half2 hh1 = __floats2half2_rn(h10, h11);
                float2 hf0 = __half22float2(hh0), hf1 = __half22float2(hh1);
                __half2 hl0 = __floats2half2_rn(h00 - hf0.x, h01v - hf0.y);
                __half2 hl1 = __floats2half2_rn(h10 - hf1.x, h11 - hf1.y);
                *(uint32_t*)(sm + r0 * ESTR + col * 2) = h2u(hh0);
                *(uint32_t*)(sm + (r0 + 8) * ESTR + col * 2) = h2u(hh1);
                *(uint32_t*)(sm + 34816 + r0 * ESTR + col * 2) = h2u(hl0);
                *(uint32_t*)(sm + 34816 + (r0 + 8) * ESTR + col * 2) = h2u(hl1);
            }
        }
        __syncthreads();              // (B)
    }

    // ======== fused output projection: all 16 warps ========
    {
        int em = (wid >> 2) * 32;
        int en = (wid & 3) * 32;
        uint32_t ahh = sbase + (uint32_t)(em + (lane & 15)) * ESTR + (lane >> 4) * 16;
        uint32_t ahl = ahh + 34816;
        uint32_t bwh = sbase + 69632 +
            (uint32_t)(en + (lane & 7) + ((lane >> 4) & 1) * 8) * ESTR +
            ((lane >> 3) & 1) * 16;
        uint32_t bwl = bwh + 34816;

        float o2[2][4][4];
        #pragma unroll
        for (int mi = 0; mi < 2; mi++)
            #pragma unroll
            for (int n8 = 0; n8 < 4; n8++)
                #pragma unroll
                for (int x = 0; x < 4; x++) o2[mi][n8][x] = 0.f;

        #pragma unroll
        for (int kk = 0; kk < 8; kk++) {
            uint32_t ah[2][4], al[2][4];
            #pragma unroll
            for (int mi = 0; mi < 2; mi++) {
                ldsm_x4(ah[mi], ahh + mi * 16 * ESTR + kk * 32);
                ldsm_x4(al[mi], ahl + mi * 16 * ESTR + kk * 32);
            }
            #pragma unroll
            for (int nb = 0; nb < 2; nb++) {
                uint32_t bh[4], bl[4];
                ldsm_x4(bh, bwh + nb * 16 * ESTR + kk * 32);
                ldsm_x4(bl, bwl + nb * 16 * ESTR + kk * 32);
                #pragma unroll
                for (int mi = 0; mi < 2; mi++) {
                    mma16816(o2[mi][nb * 2 + 0], ah[mi], bh + 0);
                    mma16816(o2[mi][nb * 2 + 1], ah[mi], bh + 2);
                    mma16816(o2[mi][nb * 2 + 0], al[mi], bh + 0);
                    mma16816(o2[mi][nb * 2 + 1], al[mi], bh + 2);
                    mma16816(o2[mi][nb * 2 + 0], ah[mi], bl + 0);
                    mma16816(o2[mi][nb * 2 + 1], ah[mi], bl + 2);
                }
            }
        }

        #pragma unroll
        for (int mi = 0; mi < 2; mi++) {
            int r0 = em + mi * 16 + (lane >> 2);
            #pragma unroll
            for (int n8 = 0; n8 < 4; n8++) {
                int col = en + n8 * 8 + (lane & 3) * 2;
                float2 v0 = make_float2(leaky(o2[mi][n8][0]), leaky(o2[mi][n8][1]));
                float2 v1 = make_float2(leaky(o2[mi][n8][2]), leaky(o2[mi][n8][3]));
                *(float2*)(out + (size_t)(b * NN + it0 + r0) * FF + col) = v0;
                *(float2*)(out + (size_t)(b * NN + it0 + r0 + 8) * FF + col) = v1;
            }
        }
    }
}

// ---------------- launch ----------------
extern "C" void kernel_launch(void* const* d_in, const int* in_sizes, int n_in,
                              void* d_out, int out_size) {
    const float* q    = (const float*)d_in[0];
    const float* k    = (const float*)d_in[1];
    const float* v    = (const float*)d_in[2];
    const int*   adj  = (const int*)  d_in[3];
    const float* Wq_w = (const float*)d_in[4];
    const float* Wq_b = (const float*)d_in[5];
    const float* Wk_w = (const float*)d_in[6];
    const float* Wk_b = (const float*)d_in[7];
    const float* Wv_w = (const float*)d_in[8];
    const float* Wv_b = (const float*)d_in[9];
    const float* a    = (const float*)d_in[10];
    const float* Wo_w = (const float*)d_in[11];
    float* out = (float*)d_out;

    void* vph_ptr = nullptr;
    cudaGetSymbolAddress(&vph_ptr, g_vph);

    static cudaStream_t s1 = nullptr;
    static cudaEvent_t evFork = nullptr, evJoin = nullptr;
    if (!s1) {
        cudaStreamCreateWithFlags(&s1, cudaStreamNonBlocking);
        cudaEventCreateWithFlags(&evFork, cudaEventDisableTiming);
        cudaEventCreateWithFlags(&evJoin, cudaEventDisableTiming);
    }

    cudaFuncSetAttribute(k_attn_mma, cudaFuncAttributeMaxDynamicSharedMemorySize, SM_TOTAL);
    cudaFuncSetAttribute(k_gemm_tc, cudaFuncAttributeMaxDynamicSharedMemorySize, G_TOTAL);

    cudaEventRecord(evFork, 0);
    cudaStreamWaitEvent(s1, evFork, 0);
    k_pack<<<(BB * NN * NN) / (256 * 8), 256, 0, s1>>>(adj);

    k_prep<<<1, 128>>>(Wq_w, Wq_b, Wk_w, Wk_b, a);
    k_wh<<<(2 * BB * NN) / 8, 256>>>(q, k);
    k_gemm_tc<<<BB * NN / 128, 256, G_TOTAL>>>(v, Wv_w, Wv_b, (__half*)vph_ptr);
    k_wo<<<1, 256>>>(Wo_w);

    cudaEventRecord(evJoin, s1);
    cudaStreamWaitEvent(0, evJoin, 0);

    {
        dim3 grid(NN / 128, BB);
        k_attn_mma<<<grid, 512, SM_TOTAL>>>(out);
    }
}